// round 15
// baseline (speedup 1.0000x reference)
#include <cuda_runtime.h>
#include <cstdint>

#define NROW     256
#define S_STEPS  4001
#define M_STEPS  4000
#define NCHUNK   148
#define CLEN     28
#define CODE_UP   300
#define CODE_NONE 301
#define RINF     (1<<20)
#define NTHR     512
#define NLEAF    8

// ---- device scratch (zero-init at load; no allocations) ----
// Transposed G: g_GT[(c+1)*NROW + i] = G(i,c), c in [-1..i].
__device__ __align__(16) float g_GT[(NROW + 1) * NROW];
__device__ int   g_sum_r[NCHUNK * NROW];        // per-chunk transform: forced value (RINF = pass)
__device__ int   g_sum_K[NCHUNK];               // per-chunk transform: min-clamp
// hierarchical barrier: 8 leaf counters on disjoint 128B lines + root + gen
__device__ unsigned g_leaf[NLEAF * 32];         // counters at stride 32 ints = 128B
__device__ unsigned g_root;
__device__ volatile unsigned g_gen;             // generation (monotonic across replays)

__device__ __forceinline__ float xval(int i) {
    if (i >= 255) return 1.0f;
    if (i <= 0)   return 0.0f;
    return (float)i * (1.0f / 255.0f);
}

__device__ __forceinline__ float hnorm(const float* __restrict__ hd, int s) {
    return (s == 0) ? 1.0f : (hd[s - 1] + 1.0f) * 0.5f;
}

// classify step s: up (h>p), down (h<p, code=jmax), or none
__device__ __forceinline__ void make_step(const float* __restrict__ hd, int s,
                                          float& h, int& code) {
    h = hnorm(hd, s);
    int pi = (s == 0) ? (S_STEPS - 1) : (s - 1);
    float p = hnorm(hd, pi);
    if (h > p) {
        code = CODE_UP;
    } else if (h < p) {
        int jm = (int)(h * 255.0f);
        if (jm > 255) jm = 255;
        if (jm < 0)   jm = 0;
        while (jm < 255 && xval(jm + 1) <= h) ++jm;   // exact float semantics
        while (jm >= 0 && xval(jm) > h)      --jm;
        code = jm;                                    // jmax in [-1, 255]
    } else {
        code = CODE_NONE;
    }
}

// jax.nn.softplus = max(x,0) + log1p(exp(-|x|))
__device__ __forceinline__ float softplus_f(float x) {
    return fmaxf(x, 0.0f) + log1pf(expf(-fabsf(x)));
}

// transform compose: t_out = t2 ∘ t1 (t1 applied first)
__device__ __forceinline__ void comp(int r1, int K1, int r2, int K2, int& r, int& K) {
    r = (r2 != RINF) ? r2 : ((r1 != RINF) ? min(r1, K2) : RINF);
    K = min(K1, K2);
}

// 2-level grid barrier — safe: 148 CTAs, 1/SM, all resident in one wave.
// Leaf j receives 19 arrivals for j<4, 18 for j>=4 (148 = 4*19 + 4*18).
__device__ __forceinline__ void grid_barrier(int k) {
    __syncthreads();
    if (threadIdx.x == 0) {
        __threadfence();                              // release phase-A writes
        unsigned start = g_gen;                       // read BEFORE arriving
        int leaf = k & (NLEAF - 1);
        unsigned leafcnt = 18u + (leaf < 4 ? 1u : 0u);
        unsigned old = atomicAdd(&g_leaf[leaf * 32], 1u);
        if (old == leafcnt - 1) {                     // last in this leaf
            unsigned r = atomicAdd(&g_root, 1u);
            if (r == NLEAF - 1) {                     // last leaf overall
                #pragma unroll
                for (int j = 0; j < NLEAF; j++) g_leaf[j * 32] = 0;
                g_root = 0;
                __threadfence();
                atomicAdd((unsigned*)&g_gen, 1u);     // publish
            }
        }
        while (g_gen == start) __nanosleep(32);       // backoff is load-bearing
        __threadfence();                              // acquire
    }
    __syncthreads();
}

__global__ void __launch_bounds__(NTHR, 1)
kFused(const float* __restrict__ raw, const float* __restrict__ hd,
       float* __restrict__ out) {
    int k = blockIdx.x, tid = threadIdx.x;
    int half = tid >> 8;
    int t8   = tid & 255;
    int lnl  = t8 & 31;
    int wl   = t8 >> 5;
    int w    = tid >> 5;
    int ln   = tid & 31;

    __shared__ float sh[CLEN];
    __shared__ int   sc[CLEN];
    __shared__ float wtot[16];
    __shared__ float awt[8];                 // partial sums for 'a'
    __shared__ int   sR[NROW], sKm[NROW];    // upper half's compose transform
    __shared__ int   sC[NROW];               // combined entry state
    __shared__ float mat[CLEN * NROW];

    // ---- step descriptors for this block's chunk ----
    if (tid < CLEN) {
        int s = k * CLEN + tid;
        float h = 0.0f; int code = CODE_NONE;
        if (s < S_STEPS) make_step(hd, s, h, code);
        sh[tid] = h; sc[tid] = code;
    }

    // ---- phase A1: both G rows concurrently (one per 256-thread half) ----
    {
        int i = k + half * NCHUNK;
        bool valid = (i < NROW);
        float v = 0.0f;
        if (valid && t8 <= i) v = softplus_f(__ldg(raw + i * (i + 1) / 2 + t8));

        float s = v;
        #pragma unroll
        for (int o = 1; o < 32; o <<= 1) {
            float t = __shfl_up_sync(0xffffffffu, s, o);
            if (lnl >= o) s += t;
        }
        if (lnl == 31) wtot[half * 8 + wl] = s;
        __syncthreads();
        if (wl == 0) {
            float t = (lnl < 8) ? wtot[half * 8 + lnl] : 0.0f;
            #pragma unroll
            for (int o = 1; o < 8; o <<= 1) {
                float u = __shfl_up_sync(0xffffffffu, t, o);
                if (lnl >= o) t += u;
            }
            if (lnl < 8) wtot[half * 8 + lnl] = t;
        }
        __syncthreads();
        float pre = s + ((wl > 0) ? wtot[half * 8 + wl - 1] : 0.0f);
        float R = wtot[half * 8 + 7];

        if (valid) {
            // transposed store: G_T[(c+1)*NROW + i], c = t8
            if (t8 <= i) g_GT[(t8 + 1) * NROW + i] = 2.0f * pre - R;
            if (t8 == 0) g_GT[i] = -R;       // c = -1 plane (coalesced reads later)
        }
    }

    // ---- phase A2: chunk summary (lower half; sh/sc covered by A1 syncs) ----
    if (half == 0) {
        float xi = xval(t8);
        int r = RINF, K = RINF;
        #pragma unroll
        for (int l = 0; l < CLEN; l++) {
            int cd = sc[l];
            if (cd == CODE_UP) {
                if (xi < sh[l]) r = t8;
            } else if (cd != CODE_NONE) {
                if (r != RINF) r = min(r, cd);
                K = min(K, cd);
            }
        }
        g_sum_r[k * NROW + t8] = r;
        if (t8 == 0) g_sum_K[k] = K;
    }

    // ---- grid barrier: all G planes + summaries visible ----
    grid_barrier(k);

    // ---- compose split: lower composes [0,kmid), upper [kmid,k) ----
    {
        int kmid = k >> 1;
        int lo = half ? kmid : 0;
        int hi = half ? k : kmid;

        int R = RINF, Kc = RINF;
        const int* rr = g_sum_r + t8;
        int kk = lo;
        for (; kk + 8 <= hi; kk += 8) {
            int r0 = rr[(kk + 0) * NROW], r1 = rr[(kk + 1) * NROW];
            int r2 = rr[(kk + 2) * NROW], r3 = rr[(kk + 3) * NROW];
            int r4 = rr[(kk + 4) * NROW], r5 = rr[(kk + 5) * NROW];
            int r6 = rr[(kk + 6) * NROW], r7 = rr[(kk + 7) * NROW];
            int K0 = __ldg(g_sum_K + kk + 0), K1 = __ldg(g_sum_K + kk + 1);
            int K2 = __ldg(g_sum_K + kk + 2), K3 = __ldg(g_sum_K + kk + 3);
            int K4 = __ldg(g_sum_K + kk + 4), K5 = __ldg(g_sum_K + kk + 5);
            int K6 = __ldg(g_sum_K + kk + 6), K7 = __ldg(g_sum_K + kk + 7);
            int ra, Ka, rb, Kb, rc2, Kc2, rd, Kd, re, Ke, rf, Kf, rg, Kg;
            comp(r0, K0, r1, K1, ra, Ka);
            comp(r2, K2, r3, K3, rb, Kb);
            comp(r4, K4, r5, K5, rc2, Kc2);
            comp(r6, K6, r7, K7, rd, Kd);
            comp(ra, Ka, rb, Kb, re, Ke);
            comp(rc2, Kc2, rd, Kd, rf, Kf);
            comp(re, Ke, rf, Kf, rg, Kg);
            comp(R, Kc, rg, Kg, R, Kc);
        }
        for (; kk < hi; kk++) {
            comp(R, Kc, rr[kk * NROW], __ldg(g_sum_K + kk), R, Kc);
        }
        if (half == 1) { sR[t8] = R; sKm[t8] = Kc; }
        __syncthreads();
        if (half == 0) {
            int c = -1;
            c = (R != RINF) ? R : min(c, Kc);       // apply [0,kmid)
            int Rh = sR[t8], Kh = sKm[t8];
            c = (Rh != RINF) ? Rh : min(c, Kh);     // apply [kmid,k)
            sC[t8] = c;
        }
        __syncthreads();
    }

    // ---- phase C: ALU c-chain + unconditional transposed gather ----
    if (half == 0) {
        int i = t8;
        float xi = xval(i);

        // 'a' contribution: R_i = -G(i,-1) = -g_GT[i]  (fully coalesced)
        float v = -__ldg(g_GT + i);
        #pragma unroll
        for (int o = 16; o; o >>= 1) v += __shfl_xor_sync(0xffffffffu, v, o);
        if (lnl == 0) awt[wl] = v;

        int c = sC[i];
        float gv[CLEN];
        #pragma unroll
        for (int l = 0; l < CLEN; l++) {
            int cd = sc[l];
            if (cd == CODE_UP) {
                if (xi < sh[l]) c = i;
            } else if (cd != CODE_NONE) {
                c = min(c, cd);
            }
            gv[l] = __ldg(g_GT + (c + 1) * NROW + i);
        }
        #pragma unroll
        for (int l = 0; l < CLEN; l++) mat[l * NROW + i] = gv[l];
    }
    __syncthreads();

    // ---- epilogue over 16 warps: warp w reduces steps l = w, w+16 ----
    float asum = 0.0f;
    #pragma unroll
    for (int j = 0; j < 8; j++) asum += awt[j];
    float ainv = 1.0f / asum;

    for (int l = w; l < CLEN; l += 16) {
        int s = k * CLEN + l;
        const float* row = mat + l * NROW;
        float t = 0.0f;
        #pragma unroll
        for (int j = 0; j < 8; j++) t += row[ln + 32 * j];
        #pragma unroll
        for (int o = 16; o; o >>= 1) t += __shfl_xor_sync(0xffffffffu, t, o);
        if (ln == 0 && s >= 1 && s < S_STEPS) out[s - 1] = t * ainv;
    }
}

extern "C" void kernel_launch(void* const* d_in, const int* in_sizes, int n_in,
                              void* d_out, int out_size) {
    const float* hd  = (const float*)d_in[0];
    const float* raw = (const float*)d_in[1];
    if (n_in >= 2 && in_sizes[0] != M_STEPS) {
        const float* t = hd; hd = raw; raw = t;
    }
    float* out = (float*)d_out;

    kFused<<<NCHUNK, NTHR>>>(raw, hd, out);
}

// round 16
// speedup vs baseline: 1.0722x; 1.0722x over previous
#include <cuda_runtime.h>
#include <cstdint>

#define NROW     256
#define S_STEPS  4001
#define M_STEPS  4000
#define NCHUNK   148
#define CLEN     28
#define CODE_UP   300
#define CODE_NONE 301
#define RINF     (1<<20)
#define NTHR     512

// ---- device scratch (zero-init at load; no allocations) ----
// Transposed G: g_GT[(c+1)*NROW + i] = G(i,c), c in [-1..i].
__device__ __align__(16) float g_GT[(NROW + 1) * NROW];
__device__ int   g_sum_r[NCHUNK * NROW];        // per-chunk transform: forced value (RINF = pass)
__device__ int   g_sum_K[NCHUNK];               // per-chunk transform: min-clamp
// per-block monotonic done-flags, 128B stride. Invariant: all equal at the
// start of every kernel execution (each block +1 exactly once per run).
__device__ unsigned g_flag[NCHUNK * 32];

__device__ __forceinline__ float xval(int i) {
    if (i >= 255) return 1.0f;
    if (i <= 0)   return 0.0f;
    return (float)i * (1.0f / 255.0f);
}

__device__ __forceinline__ float hnorm(const float* __restrict__ hd, int s) {
    return (s == 0) ? 1.0f : (hd[s - 1] + 1.0f) * 0.5f;
}

// classify step s: up (h>p), down (h<p, code=jmax), or none
__device__ __forceinline__ void make_step(const float* __restrict__ hd, int s,
                                          float& h, int& code) {
    h = hnorm(hd, s);
    int pi = (s == 0) ? (S_STEPS - 1) : (s - 1);
    float p = hnorm(hd, pi);
    if (h > p) {
        code = CODE_UP;
    } else if (h < p) {
        int jm = (int)(h * 255.0f);
        if (jm > 255) jm = 255;
        if (jm < 0)   jm = 0;
        while (jm < 255 && xval(jm + 1) <= h) ++jm;   // exact float semantics
        while (jm >= 0 && xval(jm) > h)      --jm;
        code = jm;                                    // jmax in [-1, 255]
    } else {
        code = CODE_NONE;
    }
}

// jax.nn.softplus = max(x,0) + log1p(exp(-|x|))
__device__ __forceinline__ float softplus_f(float x) {
    return fmaxf(x, 0.0f) + log1pf(expf(-fabsf(x)));
}

// transform compose: t_out = t2 ∘ t1 (t1 applied first)
__device__ __forceinline__ void comp(int r1, int K1, int r2, int K2, int& r, int& K) {
    r = (r2 != RINF) ? r2 : ((r1 != RINF) ? min(r1, K2) : RINF);
    K = min(K1, K2);
}

__device__ __forceinline__ unsigned ld_acq(const unsigned* p) {
    unsigned v;
    asm volatile("ld.acquire.gpu.global.u32 %0, [%1];" : "=r"(v) : "l"(p) : "memory");
    return v;
}

__global__ void __launch_bounds__(NTHR, 1)
kFused(const float* __restrict__ raw, const float* __restrict__ hd,
       float* __restrict__ out) {
    int k = blockIdx.x, tid = threadIdx.x;
    int half = tid >> 8;
    int t8   = tid & 255;
    int lnl  = t8 & 31;
    int wl   = t8 >> 5;
    int w    = tid >> 5;
    int ln   = tid & 31;

    __shared__ float sh[CLEN];
    __shared__ int   sc[CLEN];
    __shared__ float wtot[16];
    __shared__ float awt[8];                 // partial sums for 'a'
    __shared__ int   sR[NROW], sKm[NROW];    // upper half's compose transform
    __shared__ int   sC[NROW];               // combined entry state
    __shared__ float mat[CLEN * NROW];
    __shared__ unsigned s_target;

    // ---- step descriptors for this block's chunk ----
    if (tid < CLEN) {
        int s = k * CLEN + tid;
        float h = 0.0f; int code = CODE_NONE;
        if (s < S_STEPS) make_step(hd, s, h, code);
        sh[tid] = h; sc[tid] = code;
    }

    // ---- phase A1: both G rows concurrently (one per 256-thread half) ----
    {
        int i = k + half * NCHUNK;
        bool valid = (i < NROW);
        float v = 0.0f;
        if (valid && t8 <= i) v = softplus_f(__ldg(raw + i * (i + 1) / 2 + t8));

        float s = v;
        #pragma unroll
        for (int o = 1; o < 32; o <<= 1) {
            float t = __shfl_up_sync(0xffffffffu, s, o);
            if (lnl >= o) s += t;
        }
        if (lnl == 31) wtot[half * 8 + wl] = s;
        __syncthreads();
        if (wl == 0) {
            float t = (lnl < 8) ? wtot[half * 8 + lnl] : 0.0f;
            #pragma unroll
            for (int o = 1; o < 8; o <<= 1) {
                float u = __shfl_up_sync(0xffffffffu, t, o);
                if (lnl >= o) t += u;
            }
            if (lnl < 8) wtot[half * 8 + lnl] = t;
        }
        __syncthreads();
        float pre = s + ((wl > 0) ? wtot[half * 8 + wl - 1] : 0.0f);
        float R = wtot[half * 8 + 7];

        if (valid) {
            // transposed store: G_T[(c+1)*NROW + i], c = t8
            if (t8 <= i) g_GT[(t8 + 1) * NROW + i] = 2.0f * pre - R;
            if (t8 == 0) g_GT[i] = -R;       // c = -1 plane (coalesced reads later)
        }
    }

    // ---- phase A2: chunk summary (lower half; sh/sc covered by A1 syncs) ----
    if (half == 0) {
        float xi = xval(t8);
        int r = RINF, K = RINF;
        #pragma unroll
        for (int l = 0; l < CLEN; l++) {
            int cd = sc[l];
            if (cd == CODE_UP) {
                if (xi < sh[l]) r = t8;
            } else if (cd != CODE_NONE) {
                if (r != RINF) r = min(r, cd);
                K = min(K, cd);
            }
        }
        g_sum_r[k * NROW + t8] = r;
        if (t8 == 0) g_sum_K[k] = K;
    }

    // ---- publish this block's done-flag (release) ----
    __syncthreads();                         // all phase-A stores issued
    if (tid == 0) {
        __threadfence();                     // release (gpu scope)
        s_target = atomicAdd(&g_flag[k * 32], 1u) + 1u;
    }
    __syncthreads();
    unsigned target = s_target;

    // ---- wait 1: predecessors [0,k) only (parallel: one flag per thread) ----
    if (half == 0 && t8 < k) {
        while (ld_acq(&g_flag[t8 * 32]) < target) __nanosleep(32);
    }
    __syncthreads();                         // acquire propagates via barrier

    // ---- compose split: lower composes [0,kmid), upper [kmid,k) ----
    {
        int kmid = k >> 1;
        int lo = half ? kmid : 0;
        int hi = half ? k : kmid;

        int R = RINF, Kc = RINF;
        const int* rr = g_sum_r + t8;
        int kk = lo;
        for (; kk + 8 <= hi; kk += 8) {
            int r0 = rr[(kk + 0) * NROW], r1 = rr[(kk + 1) * NROW];
            int r2 = rr[(kk + 2) * NROW], r3 = rr[(kk + 3) * NROW];
            int r4 = rr[(kk + 4) * NROW], r5 = rr[(kk + 5) * NROW];
            int r6 = rr[(kk + 6) * NROW], r7 = rr[(kk + 7) * NROW];
            int K0 = __ldg(g_sum_K + kk + 0), K1 = __ldg(g_sum_K + kk + 1);
            int K2 = __ldg(g_sum_K + kk + 2), K3 = __ldg(g_sum_K + kk + 3);
            int K4 = __ldg(g_sum_K + kk + 4), K5 = __ldg(g_sum_K + kk + 5);
            int K6 = __ldg(g_sum_K + kk + 6), K7 = __ldg(g_sum_K + kk + 7);
            int ra, Ka, rb, Kb, rc2, Kc2, rd, Kd, re, Ke, rf, Kf, rg, Kg;
            comp(r0, K0, r1, K1, ra, Ka);
            comp(r2, K2, r3, K3, rb, Kb);
            comp(r4, K4, r5, K5, rc2, Kc2);
            comp(r6, K6, r7, K7, rd, Kd);
            comp(ra, Ka, rb, Kb, re, Ke);
            comp(rc2, Kc2, rd, Kd, rf, Kf);
            comp(re, Ke, rf, Kf, rg, Kg);
            comp(R, Kc, rg, Kg, R, Kc);
        }
        for (; kk < hi; kk++) {
            comp(R, Kc, rr[kk * NROW], __ldg(g_sum_K + kk), R, Kc);
        }
        if (half == 1) { sR[t8] = R; sKm[t8] = Kc; }
        __syncthreads();
        if (half == 0) {
            int c = -1;
            c = (R != RINF) ? R : min(c, Kc);       // apply [0,kmid)
            int Rh = sR[t8], Kh = sKm[t8];
            c = (Rh != RINF) ? Rh : min(c, Kh);     // apply [kmid,k)
            sC[t8] = c;
        }
    }

    // ---- wait 2: remaining blocks [k,148) — largely overlapped by compose ----
    if (half == 0 && t8 >= k && t8 < NCHUNK) {
        while (ld_acq(&g_flag[t8 * 32]) < target) __nanosleep(32);
    }
    __syncthreads();

    // ---- phase C: ALU c-chain + unconditional transposed gather ----
    if (half == 0) {
        int i = t8;
        float xi = xval(i);

        // 'a' contribution: R_i = -G(i,-1) = -g_GT[i]  (fully coalesced)
        float v = -__ldg(g_GT + i);
        #pragma unroll
        for (int o = 16; o; o >>= 1) v += __shfl_xor_sync(0xffffffffu, v, o);
        if (lnl == 0) awt[wl] = v;

        int c = sC[i];
        float gv[CLEN];
        #pragma unroll
        for (int l = 0; l < CLEN; l++) {
            int cd = sc[l];
            if (cd == CODE_UP) {
                if (xi < sh[l]) c = i;
            } else if (cd != CODE_NONE) {
                c = min(c, cd);
            }
            gv[l] = __ldg(g_GT + (c + 1) * NROW + i);
        }
        #pragma unroll
        for (int l = 0; l < CLEN; l++) mat[l * NROW + i] = gv[l];
    }
    __syncthreads();

    // ---- epilogue over 16 warps: warp w reduces steps l = w, w+16 ----
    float asum = 0.0f;
    #pragma unroll
    for (int j = 0; j < 8; j++) asum += awt[j];
    float ainv = 1.0f / asum;

    for (int l = w; l < CLEN; l += 16) {
        int s = k * CLEN + l;
        const float* row = mat + l * NROW;
        float t = 0.0f;
        #pragma unroll
        for (int j = 0; j < 8; j++) t += row[ln + 32 * j];
        #pragma unroll
        for (int o = 16; o; o >>= 1) t += __shfl_xor_sync(0xffffffffu, t, o);
        if (ln == 0 && s >= 1 && s < S_STEPS) out[s - 1] = t * ainv;
    }
}

extern "C" void kernel_launch(void* const* d_in, const int* in_sizes, int n_in,
                              void* d_out, int out_size) {
    const float* hd  = (const float*)d_in[0];
    const float* raw = (const float*)d_in[1];
    if (n_in >= 2 && in_sizes[0] != M_STEPS) {
        const float* t = hd; hd = raw; raw = t;
    }
    float* out = (float*)d_out;

    kFused<<<NCHUNK, NTHR>>>(raw, hd, out);
}

// round 17
// speedup vs baseline: 1.1197x; 1.0443x over previous
#include <cuda_runtime.h>
#include <cstdint>

#define NROW     256
#define S_STEPS  4001
#define M_STEPS  4000
#define NCHUNK   148
#define CLEN     28
#define CODE_UP   300
#define CODE_NONE 301
#define RINF     (1<<20)
#define NTHR     512
#define NGRP     9            // group leaders: blocks 0,16,...,128 (group 9 never consumed)

// ---- device scratch (zero-init at load; no allocations) ----
// Transposed G: g_GT[(c+1)*NROW + i] = G(i,c), c in [-1..i].
__device__ __align__(16) float g_GT[(NROW + 1) * NROW];
__device__ int   g_sum_r[NCHUNK * NROW];        // per-chunk transform: forced value (RINF = pass)
__device__ int   g_sum_K[NCHUNK];               // per-chunk transform: min-clamp
__device__ int   g_grp_r[NGRP * NROW];          // 16-chunk group transforms
__device__ int   g_grp_K[NGRP];
// per-block monotonic flags, 128B stride. Every block nets +2 per run:
// leaders: phaseA(+1), group publish(+1). others: phaseA(+1), end(+1).
__device__ unsigned g_flag[NCHUNK * 32];

__device__ __forceinline__ float xval(int i) {
    if (i >= 255) return 1.0f;
    if (i <= 0)   return 0.0f;
    return (float)i * (1.0f / 255.0f);
}

__device__ __forceinline__ float hnorm(const float* __restrict__ hd, int s) {
    return (s == 0) ? 1.0f : (hd[s - 1] + 1.0f) * 0.5f;
}

// classify step s: up (h>p), down (h<p, code=jmax), or none
__device__ __forceinline__ void make_step(const float* __restrict__ hd, int s,
                                          float& h, int& code) {
    h = hnorm(hd, s);
    int pi = (s == 0) ? (S_STEPS - 1) : (s - 1);
    float p = hnorm(hd, pi);
    if (h > p) {
        code = CODE_UP;
    } else if (h < p) {
        int jm = (int)(h * 255.0f);
        if (jm > 255) jm = 255;
        if (jm < 0)   jm = 0;
        while (jm < 255 && xval(jm + 1) <= h) ++jm;   // exact float semantics
        while (jm >= 0 && xval(jm) > h)      --jm;
        code = jm;                                    // jmax in [-1, 255]
    } else {
        code = CODE_NONE;
    }
}

// jax.nn.softplus = max(x,0) + log1p(exp(-|x|))
__device__ __forceinline__ float softplus_f(float x) {
    return fmaxf(x, 0.0f) + log1pf(expf(-fabsf(x)));
}

// transform compose: t_out = t2 ∘ t1 (t1 applied first)
__device__ __forceinline__ void comp(int r1, int K1, int r2, int K2, int& r, int& K) {
    r = (r2 != RINF) ? r2 : ((r1 != RINF) ? min(r1, K2) : RINF);
    K = min(K1, K2);
}

__device__ __forceinline__ unsigned ld_acq(const unsigned* p) {
    unsigned v;
    asm volatile("ld.acquire.gpu.global.u32 %0, [%1];" : "=r"(v) : "l"(p) : "memory");
    return v;
}

// compose chunk transforms [lo, min(lo+16,limit)) via fully-unrolled predicated
// load tree: all <=16 loads issue before any compose (identity = (RINF,RINF))
__device__ __forceinline__ void compose_chunks16(int lo, int limit, int t8,
                                                 int& Ro, int& Ko) {
    int r[16], q[16];
    #pragma unroll
    for (int j = 0; j < 16; j++) {
        int cc = lo + j;
        bool a = cc < limit;
        r[j] = a ? __ldg(g_sum_r + cc * NROW + t8) : RINF;
        q[j] = a ? __ldg(g_sum_K + cc)             : RINF;
    }
    #pragma unroll
    for (int st = 1; st < 16; st <<= 1)
        #pragma unroll
        for (int j = 0; j + st < 16; j += 2 * st)
            comp(r[j], q[j], r[j + st], q[j + st], r[j], q[j]);
    Ro = r[0]; Ko = q[0];
}

// compose group transforms [0, g0) (g0 <= 9), same predicated-tree pattern
__device__ __forceinline__ void compose_groups(int g0, int t8, int& Ro, int& Ko) {
    int r[NGRP], q[NGRP];
    #pragma unroll
    for (int j = 0; j < NGRP; j++) {
        bool a = j < g0;
        r[j] = a ? __ldg(g_grp_r + j * NROW + t8) : RINF;
        q[j] = a ? __ldg(g_grp_K + j)             : RINF;
    }
    #pragma unroll
    for (int st = 1; st < NGRP; st <<= 1)
        #pragma unroll
        for (int j = 0; j + st < NGRP; j += 2 * st)
            comp(r[j], q[j], r[j + st], q[j + st], r[j], q[j]);
    Ro = r[0]; Ko = q[0];
}

__global__ void __launch_bounds__(NTHR, 1)
kFused(const float* __restrict__ raw, const float* __restrict__ hd,
       float* __restrict__ out) {
    int k = blockIdx.x, tid = threadIdx.x;
    int half = tid >> 8;
    int t8   = tid & 255;
    int lnl  = t8 & 31;
    int wl   = t8 >> 5;
    int w    = tid >> 5;
    int ln   = tid & 31;

    __shared__ float sh[CLEN];
    __shared__ int   sc[CLEN];
    __shared__ float wtot[16];
    __shared__ float awt[8];                 // partial sums for 'a'
    __shared__ int   sR[NROW], sKm[NROW];    // residual transform (from upper half)
    __shared__ int   sC[NROW];               // combined entry state
    __shared__ float mat[CLEN * NROW];
    __shared__ unsigned s_target;

    // ---- step descriptors for this block's chunk ----
    if (tid < CLEN) {
        int s = k * CLEN + tid;
        float h = 0.0f; int code = CODE_NONE;
        if (s < S_STEPS) make_step(hd, s, h, code);
        sh[tid] = h; sc[tid] = code;
    }

    // ---- phase A1: both G rows concurrently (one per 256-thread half) ----
    {
        int i = k + half * NCHUNK;
        bool valid = (i < NROW);
        float v = 0.0f;
        if (valid && t8 <= i) v = softplus_f(__ldg(raw + i * (i + 1) / 2 + t8));

        float s = v;
        #pragma unroll
        for (int o = 1; o < 32; o <<= 1) {
            float t = __shfl_up_sync(0xffffffffu, s, o);
            if (lnl >= o) s += t;
        }
        if (lnl == 31) wtot[half * 8 + wl] = s;
        __syncthreads();
        if (wl == 0) {
            float t = (lnl < 8) ? wtot[half * 8 + lnl] : 0.0f;
            #pragma unroll
            for (int o = 1; o < 8; o <<= 1) {
                float u = __shfl_up_sync(0xffffffffu, t, o);
                if (lnl >= o) t += u;
            }
            if (lnl < 8) wtot[half * 8 + lnl] = t;
        }
        __syncthreads();
        float pre = s + ((wl > 0) ? wtot[half * 8 + wl - 1] : 0.0f);
        float R = wtot[half * 8 + 7];

        if (valid) {
            if (t8 <= i) g_GT[(t8 + 1) * NROW + i] = 2.0f * pre - R;
            if (t8 == 0) g_GT[i] = -R;       // c = -1 plane
        }
    }

    // ---- phase A2: chunk summary (lower half) ----
    if (half == 0) {
        float xi = xval(t8);
        int r = RINF, K = RINF;
        #pragma unroll
        for (int l = 0; l < CLEN; l++) {
            int cd = sc[l];
            if (cd == CODE_UP) {
                if (xi < sh[l]) r = t8;
            } else if (cd != CODE_NONE) {
                if (r != RINF) r = min(r, cd);
                K = min(K, cd);
            }
        }
        g_sum_r[k * NROW + t8] = r;
        if (t8 == 0) g_sum_K[k] = K;
    }

    // ---- publish flag1 (release) ----
    __syncthreads();
    if (tid == 0) {
        __threadfence();
        s_target = atomicAdd(&g_flag[k * 32], 1u) + 1u;
    }
    __syncthreads();
    unsigned target = s_target;

    int g0 = k >> 4;
    bool isgrp = ((k & 15) == 0) && (g0 < NGRP);

    // ---- group leaders: wait own 16 chunks, compose group, publish flag2 ----
    if (isgrp) {
        int hi = min(k + 16, NCHUNK);
        if (half == 0 && t8 >= 1 && t8 < hi - k) {
            while (ld_acq(&g_flag[(k + t8) * 32]) < target) __nanosleep(32);
        }
        __syncthreads();
        if (half == 0) {
            int R, K;
            compose_chunks16(k, hi, t8, R, K);
            g_grp_r[g0 * NROW + t8] = R;
            if (t8 == 0) g_grp_K[g0] = K;
        }
        __syncthreads();
        if (tid == 0) {
            __threadfence();
            atomicAdd(&g_flag[k * 32], 1u);   // flag -> F+2
        }
    }

    // ---- wait1: group leaders < g0 at flag2, residual chunks at flag1 ----
    if (half == 0) {
        if (t8 < g0) {
            while (ld_acq(&g_flag[(t8 << 4) * 32]) < target + 1u) __nanosleep(32);
        } else if (t8 >= (g0 << 4) && t8 < k) {
            while (ld_acq(&g_flag[t8 * 32]) < target) __nanosleep(32);
        }
    }
    __syncthreads();

    // ---- entry-state compose: lower = groups [0,g0), upper = residual [16*g0,k) ----
    {
        int Rg = RINF, Kg = RINF;
        if (half == 0) {
            compose_groups(g0, t8, Rg, Kg);
        } else {
            int R, K;
            compose_chunks16(g0 << 4, k, t8, R, K);
            sR[t8] = R; sKm[t8] = K;
        }
        __syncthreads();
        if (half == 0) {
            int c = -1;
            c = (Rg != RINF) ? Rg : min(c, Kg);     // apply groups [0,16*g0)
            int Rh = sR[t8], Kh = sKm[t8];
            c = (Rh != RINF) ? Rh : min(c, Kh);     // apply residual [16*g0,k)
            sC[t8] = c;
        }
    }

    // ---- wait2: all blocks' phase A (flag1) — largely overlapped above ----
    if (half == 0 && t8 >= k && t8 < NCHUNK) {
        while (ld_acq(&g_flag[t8 * 32]) < target) __nanosleep(32);
    }
    __syncthreads();

    // ---- phase C: ALU c-chain + unconditional transposed gather ----
    if (half == 0) {
        int i = t8;
        float xi = xval(i);

        // 'a' contribution: R_i = -G(i,-1) = -g_GT[i]  (coalesced)
        float v = -__ldg(g_GT + i);
        #pragma unroll
        for (int o = 16; o; o >>= 1) v += __shfl_xor_sync(0xffffffffu, v, o);
        if (lnl == 0) awt[wl] = v;

        int c = sC[i];
        float gv[CLEN];
        #pragma unroll
        for (int l = 0; l < CLEN; l++) {
            int cd = sc[l];
            if (cd == CODE_UP) {
                if (xi < sh[l]) c = i;
            } else if (cd != CODE_NONE) {
                c = min(c, cd);
            }
            gv[l] = __ldg(g_GT + (c + 1) * NROW + i);
        }
        #pragma unroll
        for (int l = 0; l < CLEN; l++) mat[l * NROW + i] = gv[l];
    }
    __syncthreads();

    // ---- epilogue over 16 warps: warp w reduces steps l = w, w+16 ----
    float asum = 0.0f;
    #pragma unroll
    for (int j = 0; j < 8; j++) asum += awt[j];
    float ainv = 1.0f / asum;

    for (int l = w; l < CLEN; l += 16) {
        int s = k * CLEN + l;
        const float* row = mat + l * NROW;
        float t = 0.0f;
        #pragma unroll
        for (int j = 0; j < 8; j++) t += row[ln + 32 * j];
        #pragma unroll
        for (int o = 16; o; o >>= 1) t += __shfl_xor_sync(0xffffffffu, t, o);
        if (ln == 0 && s >= 1 && s < S_STEPS) out[s - 1] = t * ainv;
    }

    // ---- non-leaders: equalize flag to F+2 so next replay starts uniform ----
    if (!isgrp && tid == 0) atomicAdd(&g_flag[k * 32], 1u);
}

extern "C" void kernel_launch(void* const* d_in, const int* in_sizes, int n_in,
                              void* d_out, int out_size) {
    const float* hd  = (const float*)d_in[0];
    const float* raw = (const float*)d_in[1];
    if (n_in >= 2 && in_sizes[0] != M_STEPS) {
        const float* t = hd; hd = raw; raw = t;
    }
    float* out = (float*)d_out;

    kFused<<<NCHUNK, NTHR>>>(raw, hd, out);
}